// round 8
// baseline (speedup 1.0000x reference)
#include <cuda_runtime.h>
#include <math.h>

#define VV 4
#define NN 2048
#define DD 128
#define KK 10
#define NPAIR 12
#define CAP 160            // candidate key slots per row (40 chunks x 4)
#define TAU0 0.99f         // static threshold; exact fallback covers any input
#define PROJ_BLOCKS 768
#define TOPK_BLOCKS 3072   // 8 rows per block
#define TOTAL_BLOCKS (PROJ_BLOCKS + TOPK_BLOCKS)  // 3840, bid%5==0 -> proj

// ---------------- scratch (no allocs allowed) ----------------
__device__ float g_Q[VV * NN * DD];
__device__ float g_K[VV * NN * DD];
__device__ float g_V[VV * NN * DD];
__device__ int   g_idx[NPAIR * NN * KK];
__device__ float4 g_meanV4[VV * (DD / 4)];

// total-order 64-bit key: higher value wins; ties -> lower index (matches
// lax.top_k). C >= 0 so monotonic float map is bits | signbit.
__device__ __forceinline__ unsigned long long tk_key(float x, int m)
{
    unsigned int mb = __float_as_uint(x) | 0x80000000u;
    return ((unsigned long long)mb << 32) | (unsigned int)(NN - 1 - m);
}

__device__ __forceinline__ unsigned long long wmax64(unsigned long long k)
{
#pragma unroll
    for (int off = 16; off > 0; off >>= 1) {
        unsigned long long o = __shfl_xor_sync(0xffffffffu, k, off);
        if (o > k) k = o;
    }
    return k;
}

struct ProjS {
    float Xs[32][16];
    float Ws[16][132];
};
struct TopkS {
    float4 buf[2][512];                  // double buffer: 2 x 8 KB
    unsigned long long cbuf[CAP];        // 1.25 KB
    int cnt;
};

// exact bounded-rescan fallback (rare), warp 0 only, smem-resident row
__device__ void topk_fallback_w0(const float4* rp4, int lane, int* outp)
{
    unsigned long long bound = ~0ull;
    for (int r = 0; r < KK; ++r) {
        unsigned long long cand = 0ull;
        for (int i = 0; i < 16; ++i) {
            float4 v = rp4[lane + (i << 5)];
            int mb = (lane + (i << 5)) << 2;
            unsigned long long k;
            k = tk_key(v.x, mb + 0); if (k < bound && k > cand) cand = k;
            k = tk_key(v.y, mb + 1); if (k < bound && k > cand) cand = k;
            k = tk_key(v.z, mb + 2); if (k < bound && k > cand) cand = k;
            k = tk_key(v.w, mb + 3); if (k < bound && k > cand) cand = k;
        }
        unsigned long long m = wmax64(cand);
        if (lane == 0) outp[r] = NN - 1 - (int)(m & 0xffffffffu);
        bound = m;
    }
}

// ================= fused proj (+meanV) + topk =================
__global__ __launch_bounds__(128, 8) void proj_topk_kernel(
    const float* __restrict__ aligned,
    const float* __restrict__ WQ,
    const float* __restrict__ WK,
    const float* __restrict__ WV,
    const float* __restrict__ C)
{
    __shared__ __align__(16) unsigned char smem_raw[sizeof(TopkS)];
    int bid = blockIdx.x;
    int tid = threadIdx.x;
    int warp = tid >> 5, lane = tid & 31;

    if (bid % 5 == 0) {
        // ---------------- projection GEMM: 32 rows x 128 cols ----------------
        ProjS& S = *reinterpret_cast<ProjS*>(smem_raw);
        int pb = bid / 5;                 // 0..767
        int tile = pb & 63;
        int vm   = pb >> 6;               // 0..11
        int v = vm / 3, mat = vm % 3;
        const float* W = (mat == 0 ? WQ : (mat == 1 ? WK : WV)) + (size_t)v * DD * DD;
        float* Out = (mat == 0 ? g_Q : (mat == 1 ? g_K : g_V))
                     + (size_t)v * NN * DD + (size_t)tile * 32 * DD;
        const float* X = aligned + (size_t)v * NN * DD + (size_t)tile * 32 * DD;

        float acc[8][4];
#pragma unroll
        for (int i = 0; i < 8; ++i)
#pragma unroll
            for (int c = 0; c < 4; ++c) acc[i][c] = 0.f;

        for (int d0 = 0; d0 < DD; d0 += 16) {
            {
                int r = tid >> 2, f = tid & 3;
                float4 xv = *(const float4*)(X + (size_t)r * DD + d0 + f * 4);
                *(float4*)&S.Xs[r][f * 4] = xv;
            }
#pragma unroll
            for (int j = 0; j < 4; ++j) {
                int lin = tid * 4 + j;
                int e = lin >> 2, f = lin & 3;
                float4 wv = *(const float4*)(W + (size_t)e * DD + d0 + f * 4);
                S.Ws[f * 4 + 0][e] = wv.x;
                S.Ws[f * 4 + 1][e] = wv.y;
                S.Ws[f * 4 + 2][e] = wv.z;
                S.Ws[f * 4 + 3][e] = wv.w;
            }
            __syncthreads();
#pragma unroll
            for (int dd = 0; dd < 16; ++dd) {
                float4 b = *(const float4*)&S.Ws[dd][lane * 4];
#pragma unroll
                for (int i = 0; i < 8; ++i) {
                    float a = S.Xs[warp * 8 + i][dd];
                    acc[i][0] += a * b.x;
                    acc[i][1] += a * b.y;
                    acc[i][2] += a * b.z;
                    acc[i][3] += a * b.w;
                }
            }
            __syncthreads();
        }
#pragma unroll
        for (int i = 0; i < 8; ++i) {
            float4 o = make_float4(acc[i][0], acc[i][1], acc[i][2], acc[i][3]);
            *(float4*)(Out + (size_t)(warp * 8 + i) * DD + lane * 4) = o;
        }
        if (mat == 2) {
#pragma unroll
            for (int c = 0; c < 4; ++c) {
                float s = 0.f;
#pragma unroll
                for (int i = 0; i < 8; ++i) s += acc[i][c];
                atomicAdd((float*)&g_meanV4[0] + v * DD + lane * 4 + c, s);
            }
        }
        return;
    }

    // ------- topk: block owns 8 rows, double-buffered cp.async pipeline -------
    TopkS& S = *reinterpret_cast<TopkS*>(smem_raw);
    int tb = bid - bid / 5 - 1;           // 0..3071
    int row0g = tb * 8;                   // 8 rows, same (p,q) pair (8 | NN)
    int pair = row0g / NN, n0 = row0g % NN;
    int p = pair / 3, qm = pair % 3;
    int q = qm + (qm >= p ? 1 : 0);
    const float* Crow0 = C + (((size_t)p * VV + q) * NN + n0) * (size_t)NN;

    // issue one row's 8KB as a cp.async group (all 128 threads, 4 each)
    auto issue_row = [&](int r, int slot) {
        const float4* src = (const float4*)(Crow0 + (size_t)r * NN);
#pragma unroll
        for (int j = 0; j < 4; ++j) {
            int c = tid + j * 128;
            unsigned int sa = (unsigned int)__cvta_generic_to_shared(&S.buf[slot][c]);
            asm volatile("cp.async.cg.shared.global [%0], [%1], 16;"
                         :: "r"(sa), "l"(src + c));
        }
        asm volatile("cp.async.commit_group;");
    };

    if (tid == 0) S.cnt = 0;
    issue_row(0, 0);
    issue_row(1, 1);

    unsigned int lmask = (1u << lane) - 1u;
    const unsigned int tau_hi = __float_as_uint(TAU0) | 0x80000000u;

    for (int r = 0; r < 8; ++r) {
        asm volatile("cp.async.wait_group 1;" ::: "memory");
        __syncthreads();                       // row r resident; cnt reset
        const float4* rb = S.buf[r & 1];

        // scan: warp w covers chunks [w*128, w*128+128)
#pragma unroll
        for (int i = 0; i < 4; ++i) {
            int c = warp * 128 + i * 32 + lane;
            float4 a = rb[c];
            float ma = fmaxf(fmaxf(a.x, a.y), fmaxf(a.z, a.w));
            bool hit = (ma >= TAU0);
            unsigned int bal = __ballot_sync(0xffffffffu, hit);
            if (bal) {
                int base;
                if (lane == 0) base = atomicAdd(&S.cnt, __popc(bal));
                base = __shfl_sync(0xffffffffu, base, 0);
                if (hit) {
                    int pos = (base + __popc(bal & lmask)) * 4;
                    if (pos <= CAP - 4) {
                        int mb = c << 2;
                        ulonglong2* d = (ulonglong2*)&S.cbuf[pos];
                        d[0] = make_ulonglong2(tk_key(a.x, mb + 0), tk_key(a.y, mb + 1));
                        d[1] = make_ulonglong2(tk_key(a.z, mb + 2), tk_key(a.w, mb + 3));
                    }
                }
            }
        }
        __syncthreads();                       // cbuf/cnt complete

        if (warp == 0) {
            int nslots = S.cnt * 4;
            int* outp = g_idx + (size_t)(row0g + r) * KK;
            bool ok = (nslots <= CAP);
            if (ok) {
                unsigned long long k0 = (lane       < nslots) ? S.cbuf[lane]       : 0ull;
                unsigned long long k1 = (lane + 32  < nslots) ? S.cbuf[lane + 32]  : 0ull;
                unsigned long long k2 = (lane + 64  < nslots) ? S.cbuf[lane + 64]  : 0ull;
                unsigned long long k3 = (lane + 96  < nslots) ? S.cbuf[lane + 96]  : 0ull;
                unsigned long long k4 = (lane + 128 < nslots) ? S.cbuf[lane + 128] : 0ull;
                unsigned long long cand = k0;
                if (k1 > cand) cand = k1;
                if (k2 > cand) cand = k2;
                if (k3 > cand) cand = k3;
                if (k4 > cand) cand = k4;
                unsigned long long m = 0ull;
#pragma unroll
                for (int rr = 0; rr < KK; ++rr) {
                    m = wmax64(cand);
                    if (lane == 0) outp[rr] = NN - 1 - (int)(m & 0xffffffffu);
                    if (cand == m) {           // unique keys: one winner
                        if      (k0 == m) k0 = 0ull;
                        else if (k1 == m) k1 = 0ull;
                        else if (k2 == m) k2 = 0ull;
                        else if (k3 == m) k3 = 0ull;
                        else              k4 = 0ull;
                        cand = k0;
                        if (k1 > cand) cand = k1;
                        if (k2 > cand) cand = k2;
                        if (k3 > cand) cand = k3;
                        if (k4 > cand) cand = k4;
                    }
                }
                ok = ((unsigned int)(m >> 32) >= tau_hi);
            }
            if (!ok) topk_fallback_w0(rb, lane, outp);
            if (lane == 0) S.cnt = 0;
        }
        __syncthreads();                       // select done, buffer reusable

        if (r + 2 < 8) issue_row(r + 2, r & 1);
        else asm volatile("cp.async.commit_group;");  // keep group count moving
    }
}

// ---------------- gather: one warp per (p,n), barrier-free ----------------
__global__ __launch_bounds__(256) void gather_kernel(float* __restrict__ out)
{
    __shared__ float sc[8][32];
    __shared__ float smax[8][4];
    __shared__ float ssum[8][4];

    int tid = threadIdx.x;
    int w = tid >> 5, lane = tid & 31;
    int gw = blockIdx.x * 8 + w;          // 0..8191
    int p = gw >> 11, n = gw & (NN - 1);

    // q row: lanes hold segments for 8-lane-group dots
    int sub = lane & 7, grp = lane >> 3;
    const float4* Qrow = (const float4*)g_Q + ((size_t)p * NN + n) * 32;
    float4 q4[4];
#pragma unroll
    for (int j = 0; j < 4; ++j) q4[j] = Qrow[sub + 8 * j];

    // neighbor index for lane t < 30
    int myidx = 0;
    if (lane < 3 * KK) {
        int pr = p * 3 + lane / KK;
        myidx = g_idx[((size_t)pr * NN + n) * KK + (lane % KK)];
    }

    // scores: 8 iterations x 4 rows (8 lanes per row)
#pragma unroll
    for (int it = 0; it < 8; ++it) {
        int t = it * 4 + grp;
        int tq = (t < 30) ? t : 29;
        int qm = tq / KK;
        int q = qm + (qm >= p ? 1 : 0);
        int m = __shfl_sync(0xffffffffu, myidx, t & 31);
        const float4* Kr = (const float4*)g_K + ((size_t)q * NN + m) * 32;
        float s = 0.f;
#pragma unroll
        for (int j = 0; j < 4; ++j) {
            float4 k4 = __ldg(Kr + sub + 8 * j);
            s += q4[j].x * k4.x + q4[j].y * k4.y + q4[j].z * k4.z + q4[j].w * k4.w;
        }
        s += __shfl_xor_sync(0xffffffffu, s, 1);
        s += __shfl_xor_sync(0xffffffffu, s, 2);
        s += __shfl_xor_sync(0xffffffffu, s, 4);
        if (sub == 0 && t < 30) sc[w][t] = s * 0.08838834764831845f;
    }
    __syncwarp();

    if (lane < 3) {
        float mx = -3.4e38f;
#pragma unroll
        for (int k = 0; k < KK; ++k) mx = fmaxf(mx, sc[w][lane * KK + k]);
        smax[w][lane] = mx;
    }
    __syncwarp();
    if (lane < 3 * KK) sc[w][lane] = expf(sc[w][lane] - smax[w][lane / KK]);
    __syncwarp();
    if (lane < 3) {
        float su = 0.f;
#pragma unroll
        for (int k = 0; k < KK; ++k) su += sc[w][lane * KK + k];
        ssum[w][lane] = su;
    }
    __syncwarp();
    float wt = (lane < 3 * KK) ? sc[w][lane] / ssum[w][lane / KK] : 0.f;

    // epilogue: acc over 30 weighted V rows (lane = float4 column)
    float4 mv = g_meanV4[p * 32 + lane];
    const float inv = 1.0f / NN;
    float4 acc = make_float4(mv.x * inv, mv.y * inv, mv.z * inv, mv.w * inv);
#pragma unroll
    for (int t = 0; t < 3 * KK; ++t) {
        float wb = __shfl_sync(0xffffffffu, wt, t);
        int   mb = __shfl_sync(0xffffffffu, myidx, t);
        int qm = t / KK;
        int q = qm + (qm >= p ? 1 : 0);
        float4 v4 = __ldg((const float4*)g_V + ((size_t)q * NN + mb) * 32 + lane);
        acc.x += wb * v4.x; acc.y += wb * v4.y;
        acc.z += wb * v4.z; acc.w += wb * v4.w;
    }
    ((float4*)out)[((size_t)p * NN + n) * 32 + lane] = acc;
}

// ---------------- launch ----------------
extern "C" void kernel_launch(void* const* d_in, const int* in_sizes, int n_in,
                              void* d_out, int out_size)
{
    const float* aligned = (const float*)d_in[0];
    const float* C       = (const float*)d_in[1];
    const float* WQ      = (const float*)d_in[2];
    const float* WK      = (const float*)d_in[3];
    const float* WV      = (const float*)d_in[4];
    float* out = (float*)d_out;

    void* meanp = nullptr;
    cudaGetSymbolAddress(&meanp, g_meanV4);

    cudaMemsetAsync(meanp, 0, VV * DD * sizeof(float));
    proj_topk_kernel<<<TOTAL_BLOCKS, 128>>>(aligned, WQ, WK, WV, C);
    gather_kernel<<<NN * VV / 8, 256>>>(out);
}